// round 4
// baseline (speedup 1.0000x reference)
#include <cuda_runtime.h>
#include <cuda_fp16.h>
#include <cstdint>

// ---------------- problem constants ----------------
#define B_    32
#define CIN   128
#define KNUM  8
#define COUT  128
#define HIDD  512
#define KTOT  1152          // CIN * 9
#define HWTOT 4096          // 64*64
#define NCHUNK 18           // 1152 / 64 (tap-major: 9 taps x 2 channel halves)

// ---------------- scratch (device globals; no allocs) ----------------
__device__ __align__(16) float  g_pooled[B_ * CIN];      // raw sums (divide by 4096 in MLP)
__device__ __align__(16) float  g_alphas[B_ * KNUM];
__device__ __align__(16) float  g_aggb [B_ * COUT];
// agg weights pre-laid-out for the conv: [b][chunk(18)][o(128)][cidx(64)] fp16
__device__ __align__(16) __half g_aggw [(size_t)B_ * COUT * KTOT];
// x in NHWC fp16: [b][h][w][c]
__device__ __align__(16) __half g_x16  [(size_t)B_ * HWTOT * CIN];

__device__ __forceinline__ uint32_t smem_u32(const void* p) {
    return (uint32_t)__cvta_generic_to_shared(p);
}
__device__ __forceinline__ float warpsum(float v) {
#pragma unroll
    for (int o = 16; o; o >>= 1) v += __shfl_xor_sync(0xffffffffu, v, o);
    return v;
}

// ================= kernel 0: zero the pooled accumulator =================
__global__ void zero_pool_kernel() {
    int i = blockIdx.x * 256 + threadIdx.x;
    if (i < B_ * CIN) g_pooled[i] = 0.f;
}

// ================= kernel 1: NCHW fp32 -> NHWC fp16, fused avg-pool =================
// grid (32 pos-tiles, B), 256 threads. Tile = 128 positions x 128 channels.
__global__ void __launch_bounds__(256) convert_kernel(const float* __restrict__ x) {
    __shared__ char sm[128 * 256];     // 128 pos rows x 256B (128 halves, XOR-swizzled)
    const int t = threadIdx.x;
    const int pos0 = blockIdx.x * 128;
    const int b = blockIdx.y;

    const float* xb = x + ((size_t)b * CIN) * HWTOT;

    // read phase: coalesced along positions
#pragma unroll 4
    for (int i = 0; i < 64; ++i) {
        int e = i * 256 + t;          // 16384 elements
        int c = e >> 7;
        int p = e & 127;
        float v = xb[(size_t)c * HWTOT + pos0 + p];
        int boff = p * 256 + ((c * 2) ^ ((p & 15) << 4));
        *(__half*)(sm + boff) = __float2half_rn(v);
    }
    __syncthreads();

    // pooling: threads 0..127 each own one channel, sum 128 positions from smem
    if (t < 128) {
        int c = t;
        float s = 0.f;
#pragma unroll 8
        for (int p = 0; p < 128; ++p) {
            int boff = p * 256 + ((c * 2) ^ ((p & 15) << 4));
            s += __half2float(*(const __half*)(sm + boff));
        }
        atomicAdd(&g_pooled[b * CIN + c], s);
    }
    __syncthreads();

    // write phase: NHWC coalesced 16B stores
    __half* dstb = g_x16 + ((size_t)b * HWTOT + pos0) * CIN;
#pragma unroll
    for (int i = 0; i < 8; ++i) {
        int e = i * 256 + t;          // 2048 uint4
        int p = e >> 4;
        int cc = e & 15;
        int boff = p * 256 + ((cc * 16) ^ ((p & 15) << 4));
        uint4 v = *(const uint4*)(sm + boff);
        ((uint4*)(dstb + (size_t)p * CIN))[cc] = v;
    }
}

// ================= kernel 2: MLP + scores + softmax + bias agg =================
__global__ void mlp_kernel(const float* __restrict__ prompt,
                           const float* __restrict__ w1, const float* __restrict__ b1,
                           const float* __restrict__ w2, const float* __restrict__ b2,
                           const float* __restrict__ kbias) {
    int b = blockIdx.x;
    int tid = threadIdx.x, wid = tid >> 5, lane = tid & 31;
    __shared__ float sp[CIN], sh[HIDD], ss[HIDD], ssc[KNUM], sal[KNUM];
    if (tid < CIN) sp[tid] = g_pooled[b * CIN + tid] * (1.f / (float)HWTOT);
    __syncthreads();
    for (int j = wid; j < HIDD; j += 16) {
        float p = 0.f;
        for (int c = lane; c < CIN; c += 32) p += sp[c] * w1[j * CIN + c];
        p = warpsum(p);
        if (lane == 0) sh[j] = fmaxf(p + b1[j], 0.f);
    }
    __syncthreads();
    for (int j = wid; j < HIDD; j += 16) {
        float p = 0.f;
        for (int c = lane; c < HIDD; c += 32) p += sh[c] * w2[j * HIDD + c];
        p = warpsum(p);
        if (lane == 0) ss[j] = p + b2[j];
    }
    __syncthreads();
    if (wid < KNUM) {
        float p = 0.f;
        for (int j = lane; j < HIDD; j += 32) p += ss[j] * prompt[wid * HIDD + j];
        p = warpsum(p);
        if (lane == 0) ssc[wid] = p;
    }
    __syncthreads();
    if (tid == 0) {
        float mx = -1e30f;
#pragma unroll
        for (int k = 0; k < KNUM; k++) mx = fmaxf(mx, ssc[k]);
        float den = 0.f, e[KNUM];
#pragma unroll
        for (int k = 0; k < KNUM; k++) { e[k] = expf(ssc[k] - mx); den += e[k]; }
#pragma unroll
        for (int k = 0; k < KNUM; k++) sal[k] = e[k] / den;
    }
    __syncthreads();
    if (tid < KNUM) g_alphas[b * KNUM + tid] = sal[tid];
    if (tid < COUT) {
        float a = 0.f;
#pragma unroll
        for (int k = 0; k < KNUM; k++) a += sal[k] * kbias[k * COUT + tid];
        g_aggb[b * COUT + tid] = a;
    }
}

// ================= kernel 3: weight aggregation, conv-tile layout =================
// output element e = ((kc*128 + o)*64 + cidx); source k = tap -> kw[k][o][ci][tap]
__global__ void aggw_kernel(const float* __restrict__ kw) {
    __shared__ float sal[B_ * KNUM];
    int tid = threadIdx.x;
    for (int i = tid; i < B_ * KNUM; i += 128) sal[i] = g_alphas[i];
    __syncthreads();
    int e = blockIdx.x * 128 + tid;           // < 147456
    int cidx = e & 63;
    int oc   = e >> 6;
    int o    = oc & 127;
    int kc   = oc >> 7;                       // 0..17
    int tap  = kc >> 1;                       // 0..8
    int ci   = ((kc & 1) << 6) + cidx;        // 0..127
    size_t src = (size_t)o * KTOT + ci * 9 + tap;
    float wv[KNUM];
#pragma unroll
    for (int k = 0; k < KNUM; k++) wv[k] = kw[(size_t)k * (COUT * KTOT) + src];
#pragma unroll 4
    for (int b = 0; b < B_; b++) {
        float a = 0.f;
#pragma unroll
        for (int k = 0; k < KNUM; k++) a += sal[b * KNUM + k] * wv[k];
        g_aggw[(size_t)b * (COUT * KTOT) + e] = __float2half_rn(a);
    }
}

// ================= kernel 4: implicit-GEMM conv via mma.sync (HMMA) =================
// CTA = (pos-tile of 128, sample). D[128 pos x 128 o] = sum over 18 K64 chunks.
// smem tiles use 144B row stride (16B-aligned, bank-rotating) for conflict-free ldmatrix.
#define ROWB 144

struct ConvSmem {
    union {
        struct {
            __align__(16) char A[128 * ROWB];   // 18432 B
            __align__(16) char Bt[128 * ROWB];  // 18432 B
        } t;
        float F[128 * 34];                      // epilogue transpose tile (17408 B)
    } u;
    float bias[COUT];
};

__device__ __forceinline__ void ldsm_x4(uint32_t& r0, uint32_t& r1, uint32_t& r2, uint32_t& r3,
                                        uint32_t addr) {
    asm volatile("ldmatrix.sync.aligned.m8n8.x4.shared.b16 {%0,%1,%2,%3}, [%4];"
                 : "=r"(r0), "=r"(r1), "=r"(r2), "=r"(r3) : "r"(addr));
}
__device__ __forceinline__ void ldsm_x2(uint32_t& r0, uint32_t& r1, uint32_t addr) {
    asm volatile("ldmatrix.sync.aligned.m8n8.x2.shared.b16 {%0,%1}, [%2];"
                 : "=r"(r0), "=r"(r1) : "r"(addr));
}
__device__ __forceinline__ void mma16816(float* c, uint32_t a0, uint32_t a1, uint32_t a2,
                                         uint32_t a3, uint32_t b0, uint32_t b1) {
    asm volatile(
        "mma.sync.aligned.m16n8k16.row.col.f32.f16.f16.f32 "
        "{%0,%1,%2,%3}, {%4,%5,%6,%7}, {%8,%9}, {%0,%1,%2,%3};"
        : "+f"(c[0]), "+f"(c[1]), "+f"(c[2]), "+f"(c[3])
        : "r"(a0), "r"(a1), "r"(a2), "r"(a3), "r"(b0), "r"(b1));
}

__global__ void __launch_bounds__(256) conv_kernel(float* __restrict__ out) {
    __shared__ ConvSmem sm;
    const int t    = threadIdx.x;
    const int wid  = t >> 5;
    const int lane = t & 31;
    const int tile = blockIdx.x;     // 0..31
    const int b    = blockIdx.y;     // 0..31

    if (t < COUT) sm.bias[t] = g_aggb[b * COUT + t];

    const uint32_t smA = smem_u32(sm.u.t.A);
    const uint32_t smB = smem_u32(sm.u.t.Bt);

    // A-fill ownership: row p = t&127, half = t>>7 owns 32 halves (4 x uint4)
    const int p    = t & 127;
    const int half = t >> 7;
    const int pos  = tile * 128 + p;
    const int ph   = pos >> 6;
    const int pw   = pos & 63;

    const __half* xb = g_x16 + (size_t)b * HWTOT * CIN;
    const uint4*  wb = (const uint4*)(g_aggw + (size_t)b * (COUT * KTOT));

    float acc[16][4];
#pragma unroll
    for (int nt = 0; nt < 16; ++nt)
#pragma unroll
        for (int j = 0; j < 4; ++j) acc[nt][j] = 0.f;

    const int m0 = wid * 16;         // warp's row block

    for (int kc = 0; kc < NCHUNK; ++kc) {
        const int tap = kc >> 1;
        const int r   = (tap * 11) >> 5;     // tap/3 for tap in [0,8]
        const int s   = tap - r * 3;
        const int ih  = ph + r - 1;
        const int iw  = pw + s - 1;
        const bool valid = ((unsigned)ih < 64u) & ((unsigned)iw < 64u);

        // ---- A tile: 128 rows x 64 halves (NHWC vector loads) ----
        const uint4* xr = (const uint4*)(xb + ((size_t)(ih << 6) + iw) * CIN
                                         + ((kc & 1) << 6) + (half << 5));
        const uint4 zero4 = make_uint4(0u, 0u, 0u, 0u);
#pragma unroll
        for (int j = 0; j < 4; ++j) {
            uint4 v = valid ? xr[j] : zero4;
            *(uint4*)((char*)sm.u.t.A + p * ROWB + (half << 6) + (j << 4)) = v;
        }
        // ---- B tile: one chunk = 128 o-rows x 64 halves = 1024 uint4 (16 KB) ----
        const uint4* wsrc = wb + kc * 1024;
#pragma unroll
        for (int i = 0; i < 4; ++i) {
            int idx = i * 256 + t;           // 0..1023, coalesced across threads
            uint4 v = wsrc[idx];
            int g = idx << 4;                // byte offset in chunk
            int o = g >> 7;                  // 0..127 (128 B per o-row)
            int col = g & 127;
            *(uint4*)((char*)sm.u.t.Bt + o * ROWB + col) = v;
        }
        __syncthreads();

        // ---- 4 k-steps of 16 ----
#pragma unroll
        for (int ks = 0; ks < 4; ++ks) {
            uint32_t a0, a1, a2, a3;
            uint32_t aaddr = smA + (m0 + (lane & 15)) * ROWB + (ks << 5)
                           + ((lane >> 4) << 4);
            ldsm_x4(a0, a1, a2, a3, aaddr);
#pragma unroll
            for (int nt = 0; nt < 16; ++nt) {
                uint32_t b0, b1;
                uint32_t baddr = smB + ((nt << 3) + (lane & 7)) * ROWB + (ks << 5)
                               + ((lane & 8) << 1);
                ldsm_x2(b0, b1, baddr);
                mma16816(acc[nt], a0, a1, a2, a3, b0, b1);
            }
        }
        __syncthreads();
    }

    // ---- epilogue: transpose via smem, coalesced NCHW stores ----
    float* outb = out + (size_t)b * COUT * HWTOT + tile * 128;
#pragma unroll
    for (int rr = 0; rr < 4; ++rr) {         // 32 o-columns per round
#pragma unroll
        for (int q = 0; q < 4; ++q) {
            int nt = rr * 4 + q;
            int lc = q * 8 + 2 * (lane & 3);
            int row = m0 + (lane >> 2);
            *(float2*)&sm.u.F[row * 34 + lc]       = make_float2(acc[nt][0], acc[nt][1]);
            *(float2*)&sm.u.F[(row + 8) * 34 + lc] = make_float2(acc[nt][2], acc[nt][3]);
        }
        __syncthreads();
#pragma unroll
        for (int i = 0; i < 16; ++i) {
            int e = i * 256 + t;             // 4096 elements
            int o = e >> 7;
            int pp = e & 127;
            int oo = rr * 32 + o;
            outb[(size_t)oo * HWTOT + pp] = sm.u.F[pp * 34 + o] + sm.bias[oo];
        }
        __syncthreads();
    }
}

// ================= launch =================
// Inputs identified BY SIZE (robust to metadata ordering):
//   x=16777216, prompt=4096, w1=65536, b1=512(first), w2=262144, b2=512(second),
//   kernels_weights=1179648, kernels_bias=1024
extern "C" void kernel_launch(void* const* d_in, const int* in_sizes, int n_in,
                              void* d_out, int out_size) {
    (void)out_size;
    const float* x = nullptr; const float* prompt = nullptr;
    const float* w1 = nullptr; const float* b1 = nullptr;
    const float* w2 = nullptr; const float* b2 = nullptr;
    const float* kw = nullptr; const float* kb = nullptr;
    for (int i = 0; i < n_in; ++i) {
        const float* ptr = (const float*)d_in[i];
        switch (in_sizes[i]) {
            case 16777216: x = ptr; break;
            case 4096:     prompt = ptr; break;
            case 65536:    w1 = ptr; break;
            case 262144:   w2 = ptr; break;
            case 1179648:  kw = ptr; break;
            case 1024:     kb = ptr; break;
            case 512:      if (!b1) b1 = ptr; else b2 = ptr; break;
            default: break;
        }
    }
    float* out = (float*)d_out;

    zero_pool_kernel<<<(B_ * CIN + 255) / 256, 256>>>();
    convert_kernel<<<dim3(HWTOT / 128, B_), 256>>>(x);
    mlp_kernel<<<B_, 512>>>(prompt, w1, b1, w2, b2, kb);
    aggw_kernel<<<COUT * KTOT / 128, 128>>>(kw);
    conv_kernel<<<dim3(HWTOT / 128, B_), 256>>>(out);
}

// round 5
// speedup vs baseline: 1.0686x; 1.0686x over previous
#include <cuda_runtime.h>
#include <cuda_fp16.h>
#include <cstdint>

// ---------------- problem constants ----------------
#define B_    32
#define CIN   128
#define KNUM  8
#define COUT  128
#define HIDD  512
#define KTOT  1152          // CIN * 9
#define HWTOT 4096          // 64*64
#define NCHUNK 18           // 1152 / 64 (tap-major: 9 taps x 2 channel halves)
#define ROWB  144           // smem row stride (bytes) for 64-half rows
#define ATILE (128 * ROWB)  // 18432 B
#define BUFSZ (2 * ATILE)   // A + B per stage = 36864 B
#define DYNSM (2 * BUFSZ)   // two stages = 73728 B

// ---------------- scratch (device globals; no allocs) ----------------
__device__ __align__(16) float  g_pooled[B_ * CIN];
__device__ __align__(16) float  g_alphas[B_ * KNUM];
__device__ __align__(16) float  g_aggb [B_ * COUT];
// agg weights laid out for the conv: [b][chunk(18)][o(128)][cidx(64)] fp16
__device__ __align__(16) __half g_aggw [(size_t)B_ * COUT * KTOT];
// x in NHWC fp16: [b][h][w][c]
__device__ __align__(16) __half g_x16  [(size_t)B_ * HWTOT * CIN];

__device__ __forceinline__ uint32_t smem_u32(const void* p) {
    return (uint32_t)__cvta_generic_to_shared(p);
}
__device__ __forceinline__ float warpsum(float v) {
#pragma unroll
    for (int o = 16; o; o >>= 1) v += __shfl_xor_sync(0xffffffffu, v, o);
    return v;
}

// ================= kernel 0: zero the pooled accumulator =================
__global__ void zero_pool_kernel() {
    int i = blockIdx.x * 256 + threadIdx.x;
    if (i < B_ * CIN) g_pooled[i] = 0.f;
}

// ================= kernel 1: NCHW fp32 -> NHWC fp16, fused avg-pool =================
__global__ void __launch_bounds__(256) convert_kernel(const float* __restrict__ x) {
    __shared__ char sm[128 * 256];
    const int t = threadIdx.x;
    const int pos0 = blockIdx.x * 128;
    const int b = blockIdx.y;
    const float* xb = x + ((size_t)b * CIN) * HWTOT;

#pragma unroll 4
    for (int i = 0; i < 64; ++i) {
        int e = i * 256 + t;
        int c = e >> 7;
        int p = e & 127;
        float v = xb[(size_t)c * HWTOT + pos0 + p];
        int boff = p * 256 + ((c * 2) ^ ((p & 15) << 4));
        *(__half*)(sm + boff) = __float2half_rn(v);
    }
    __syncthreads();
    if (t < 128) {
        int c = t;
        float s = 0.f;
#pragma unroll 8
        for (int p = 0; p < 128; ++p) {
            int boff = p * 256 + ((c * 2) ^ ((p & 15) << 4));
            s += __half2float(*(const __half*)(sm + boff));
        }
        atomicAdd(&g_pooled[b * CIN + c], s);
    }
    __syncthreads();
    __half* dstb = g_x16 + ((size_t)b * HWTOT + pos0) * CIN;
#pragma unroll
    for (int i = 0; i < 8; ++i) {
        int e = i * 256 + t;
        int p = e >> 4;
        int cc = e & 15;
        int boff = p * 256 + ((cc * 16) ^ ((p & 15) << 4));
        uint4 v = *(const uint4*)(sm + boff);
        ((uint4*)(dstb + (size_t)p * CIN))[cc] = v;
    }
}

// ================= kernel 2: MLP + scores + softmax + bias agg =================
__global__ void mlp_kernel(const float* __restrict__ prompt,
                           const float* __restrict__ w1, const float* __restrict__ b1,
                           const float* __restrict__ w2, const float* __restrict__ b2,
                           const float* __restrict__ kbias) {
    int b = blockIdx.x;
    int tid = threadIdx.x, wid = tid >> 5, lane = tid & 31;
    __shared__ float sp[CIN], sh[HIDD], ss[HIDD], ssc[KNUM], sal[KNUM];
    if (tid < CIN) sp[tid] = g_pooled[b * CIN + tid] * (1.f / (float)HWTOT);
    __syncthreads();
    for (int j = wid; j < HIDD; j += 16) {
        float p = 0.f;
        for (int c = lane; c < CIN; c += 32) p += sp[c] * w1[j * CIN + c];
        p = warpsum(p);
        if (lane == 0) sh[j] = fmaxf(p + b1[j], 0.f);
    }
    __syncthreads();
    for (int j = wid; j < HIDD; j += 16) {
        float p = 0.f;
        for (int c = lane; c < HIDD; c += 32) p += sh[c] * w2[j * HIDD + c];
        p = warpsum(p);
        if (lane == 0) ss[j] = p + b2[j];
    }
    __syncthreads();
    if (wid < KNUM) {
        float p = 0.f;
        for (int j = lane; j < HIDD; j += 32) p += ss[j] * prompt[wid * HIDD + j];
        p = warpsum(p);
        if (lane == 0) ssc[wid] = p;
    }
    __syncthreads();
    if (tid == 0) {
        float mx = -1e30f;
#pragma unroll
        for (int k = 0; k < KNUM; k++) mx = fmaxf(mx, ssc[k]);
        float den = 0.f, e[KNUM];
#pragma unroll
        for (int k = 0; k < KNUM; k++) { e[k] = expf(ssc[k] - mx); den += e[k]; }
#pragma unroll
        for (int k = 0; k < KNUM; k++) sal[k] = e[k] / den;
    }
    __syncthreads();
    if (tid < KNUM) g_alphas[b * KNUM + tid] = sal[tid];
    if (tid < COUT) {
        float a = 0.f;
#pragma unroll
        for (int k = 0; k < KNUM; k++) a += sal[k] * kbias[k * COUT + tid];
        g_aggb[b * COUT + tid] = a;
    }
}

// ================= kernel 3: weight aggregation (v2: coalesced both sides) ========
// Block = one o. Stage kw[k][o][:] (8 x 1152 fp32) coalesced in smem; per b compute
// all 1152 outputs into an smem repack buffer (conv k-order), store 128B segments.
__global__ void __launch_bounds__(256) aggw_kernel(const float* __restrict__ kw) {
    __shared__ float kw_s[KNUM * KTOT];          // 36864 B
    __shared__ float sal[B_ * KNUM];             // 1024 B
    __shared__ __align__(16) __half out_s[KTOT]; // 2304 B
    const int t = threadIdx.x;
    const int o = blockIdx.x;

    for (int i = t; i < KNUM * KTOT; i += 256) {
        int k = i / KTOT;
        int j = i - k * KTOT;
        kw_s[i] = kw[(size_t)k * (COUT * KTOT) + (size_t)o * KTOT + j];
    }
    sal[t] = g_alphas[t];                        // 256 == B_*KNUM
    __syncthreads();

    for (int b = 0; b < B_; ++b) {
        for (int j = t; j < KTOT; j += 256) {
            float a = 0.f;
#pragma unroll
            for (int k = 0; k < KNUM; ++k) a += sal[b * KNUM + k] * kw_s[k * KTOT + j];
            int ci = j / 9;
            int tap = j - ci * 9;
            int opos = (tap * 2 + (ci >> 6)) * 64 + (ci & 63);
            out_s[opos] = __float2half_rn(a);
        }
        __syncthreads();
        if (t < 144) {
            int seg = t >> 3, part = t & 7;      // 18 segs x 8 uint4
            *(uint4*)(g_aggw + (size_t)b * (COUT * KTOT) + seg * 8192 + o * 64 + part * 8)
                = *(const uint4*)(out_s + seg * 64 + part * 8);
        }
        __syncthreads();
    }
}

// ================= kernel 4: implicit-GEMM conv (HMMA + cp.async pipeline) =========
__device__ __forceinline__ void ldsm_x4(uint32_t& r0, uint32_t& r1, uint32_t& r2, uint32_t& r3,
                                        uint32_t addr) {
    asm volatile("ldmatrix.sync.aligned.m8n8.x4.shared.b16 {%0,%1,%2,%3}, [%4];"
                 : "=r"(r0), "=r"(r1), "=r"(r2), "=r"(r3) : "r"(addr));
}
__device__ __forceinline__ void mma16816(float* c, uint32_t a0, uint32_t a1, uint32_t a2,
                                         uint32_t a3, uint32_t b0, uint32_t b1) {
    asm volatile(
        "mma.sync.aligned.m16n8k16.row.col.f32.f16.f16.f32 "
        "{%0,%1,%2,%3}, {%4,%5,%6,%7}, {%8,%9}, {%0,%1,%2,%3};"
        : "+f"(c[0]), "+f"(c[1]), "+f"(c[2]), "+f"(c[3])
        : "r"(a0), "r"(a1), "r"(a2), "r"(a3), "r"(b0), "r"(b1));
}
__device__ __forceinline__ void cp16(uint32_t dst, const void* src, uint32_t srcsz) {
    asm volatile("cp.async.cg.shared.global [%0], [%1], 16, %2;"
                 :: "r"(dst), "l"(src), "r"(srcsz) : "memory");
}
__device__ __forceinline__ void cp_commit() {
    asm volatile("cp.async.commit_group;" ::: "memory");
}

extern __shared__ char conv_dyn[];

__global__ void __launch_bounds__(256, 2) conv_kernel(float* __restrict__ out) {
    __shared__ float bias_s[COUT];
    const int t    = threadIdx.x;
    const int wid  = t >> 5;
    const int lane = t & 31;
    const int tile = blockIdx.x;     // 0..31
    const int b    = blockIdx.y;     // 0..31

    if (t < COUT) bias_s[t] = g_aggb[b * COUT + t];

    const uint32_t dynbase = smem_u32(conv_dyn);

    // A-fill ownership: row p = t&127, half = t>>7 (64 contiguous bytes each)
    const int p    = t & 127;
    const int half = t >> 7;
    const int pos  = tile * 128 + p;
    const int ph   = pos >> 6;
    const int pw   = pos & 63;

    const __half* xb = g_x16 + (size_t)b * HWTOT * CIN;
    const uint4*  wb = (const uint4*)(g_aggw + (size_t)b * (COUT * KTOT));

    // warp tiling: 4 (M) x 2 (N); warp = M32 x N64
    const int wm = wid >> 1;
    const int wn = wid & 1;
    const int m0 = wm * 32;
    const int n0 = wn * 64;

    float acc[2][8][4];
#pragma unroll
    for (int mt = 0; mt < 2; ++mt)
#pragma unroll
        for (int nt = 0; nt < 8; ++nt)
#pragma unroll
            for (int j = 0; j < 4; ++j) acc[mt][nt][j] = 0.f;

    // ---- cp.async issue of one chunk into stage buffer ----
    auto issue = [&](int kcn) {
        const uint32_t base = dynbase + (uint32_t)(kcn & 1) * BUFSZ;
        const int tap = kcn >> 1;
        const int r   = (tap * 11) >> 5;
        const int s   = tap - r * 3;
        const int ih  = ph + r - 1;
        const int iw  = pw + s - 1;
        const bool valid = ((unsigned)ih < 64u) & ((unsigned)iw < 64u);
        const uint32_t vsz = valid ? 16u : 0u;
        const char* asrc = valid
            ? (const char*)(xb + (size_t)(ih * 64 + iw) * CIN + ((kcn & 1) << 6) + (half << 5))
            : (const char*)xb;
        uint32_t adst = base + p * ROWB + (half << 6);
#pragma unroll
        for (int j = 0; j < 4; ++j) cp16(adst + j * 16, asrc + j * 16, vsz);
        const uint4* wsrc = wb + (size_t)kcn * 1024;
        const uint32_t bbase = base + ATILE;
#pragma unroll
        for (int i = 0; i < 4; ++i) {
            int idx = i * 256 + t;
            int g = idx << 4;
            cp16(bbase + (g >> 7) * ROWB + (g & 127), (const char*)(wsrc + idx), 16u);
        }
    };

    issue(0);
    cp_commit();

    for (int kc = 0; kc < NCHUNK; ++kc) {
        if (kc < NCHUNK - 1) {
            issue(kc + 1);
            cp_commit();
            asm volatile("cp.async.wait_group 1;" ::: "memory");
        } else {
            asm volatile("cp.async.wait_group 0;" ::: "memory");
        }
        __syncthreads();

        const uint32_t base = dynbase + (uint32_t)(kc & 1) * BUFSZ;
        const uint32_t smA = base;
        const uint32_t smB = base + ATILE;
        const int g  = lane >> 3;     // ldsm address group
        const int rs = lane & 7;

#pragma unroll
        for (int ks = 0; ks < 4; ++ks) {
            uint32_t A0[4], A1[4];
            uint32_t aaddr0 = smA + (m0 + (lane & 15)) * ROWB + (ks << 5) + ((lane >> 4) << 4);
            ldsm_x4(A0[0], A0[1], A0[2], A0[3], aaddr0);
            uint32_t aaddr1 = aaddr0 + 16 * ROWB;
            ldsm_x4(A1[0], A1[1], A1[2], A1[3], aaddr1);
#pragma unroll
            for (int bt = 0; bt < 4; ++bt) {
                uint32_t b0e, b1e, b0o, b1o;
                uint32_t baddr = smB + (n0 + bt * 16 + ((g >> 1) << 3) + rs) * ROWB
                               + (ks << 5) + ((g & 1) << 4);
                ldsm_x4(b0e, b1e, b0o, b1o, baddr);
                mma16816(acc[0][2 * bt],     A0[0], A0[1], A0[2], A0[3], b0e, b1e);
                mma16816(acc[0][2 * bt + 1], A0[0], A0[1], A0[2], A0[3], b0o, b1o);
                mma16816(acc[1][2 * bt],     A1[0], A1[1], A1[2], A1[3], b0e, b1e);
                mma16816(acc[1][2 * bt + 1], A1[0], A1[1], A1[2], A1[3], b0o, b1o);
            }
        }
        __syncthreads();
    }

    // ---- epilogue: 2 rounds of 64 o-columns via smem transpose ----
    float* F = (float*)conv_dyn;               // 128 x 66 floats = 33792 B
    float* outb = out + (size_t)b * COUT * HWTOT + tile * 128;
#pragma unroll
    for (int rr = 0; rr < 2; ++rr) {
        if (wn == rr) {
#pragma unroll
            for (int mt = 0; mt < 2; ++mt)
#pragma unroll
                for (int nt = 0; nt < 8; ++nt) {
                    int row = m0 + mt * 16 + (lane >> 2);
                    int col = nt * 8 + 2 * (lane & 3);
                    *(float2*)&F[row * 66 + col]       = make_float2(acc[mt][nt][0], acc[mt][nt][1]);
                    *(float2*)&F[(row + 8) * 66 + col] = make_float2(acc[mt][nt][2], acc[mt][nt][3]);
                }
        }
        __syncthreads();
#pragma unroll
        for (int i = 0; i < 32; ++i) {
            int e = i * 256 + t;               // 8192 floats
            int ol = e >> 7;
            int pp = e & 127;
            int oo = rr * 64 + ol;
            outb[(size_t)oo * HWTOT + pp] = F[pp * 66 + ol] + bias_s[oo];
        }
        __syncthreads();
    }
}

// ================= launch =================
extern "C" void kernel_launch(void* const* d_in, const int* in_sizes, int n_in,
                              void* d_out, int out_size) {
    (void)out_size;
    const float* x = nullptr; const float* prompt = nullptr;
    const float* w1 = nullptr; const float* b1 = nullptr;
    const float* w2 = nullptr; const float* b2 = nullptr;
    const float* kw = nullptr; const float* kb = nullptr;
    for (int i = 0; i < n_in; ++i) {
        const float* ptr = (const float*)d_in[i];
        switch (in_sizes[i]) {
            case 16777216: x = ptr; break;
            case 4096:     prompt = ptr; break;
            case 65536:    w1 = ptr; break;
            case 262144:   w2 = ptr; break;
            case 1179648:  kw = ptr; break;
            case 1024:     kb = ptr; break;
            case 512:      if (!b1) b1 = ptr; else b2 = ptr; break;
            default: break;
        }
    }
    float* out = (float*)d_out;

    static bool attr_set = false;
    if (!attr_set) {
        cudaFuncSetAttribute(conv_kernel, cudaFuncAttributeMaxDynamicSharedMemorySize, DYNSM);
        attr_set = true;
    }

    zero_pool_kernel<<<(B_ * CIN + 255) / 256, 256>>>();
    convert_kernel<<<dim3(HWTOT / 128, B_), 256>>>(x);
    mlp_kernel<<<B_, 512>>>(prompt, w1, b1, w2, b2, kb);
    aggw_kernel<<<COUT, 256>>>(kw);
    conv_kernel<<<dim3(HWTOT / 128, B_), 256, DYNSM>>>(out);
}

// round 6
// speedup vs baseline: 1.1892x; 1.1129x over previous
#include <cuda_runtime.h>
#include <cuda_fp16.h>
#include <cstdint>

// ---------------- problem constants ----------------
#define B_    32
#define CIN   128
#define KNUM  8
#define COUT  128
#define HIDD  512
#define KTOT  1152          // CIN * 9
#define HWTOT 4096          // 64*64
#define NCHUNK 18           // 1152 / 64 (tap-major: 9 taps x 2 channel halves)
#define ROWB  144           // B smem row stride (bytes)
#define BTILE (128 * ROWB)  // 18432 B per B stage
// conv smem layout (dynamic):
#define XSSZ  (6 * 64 * 256)          // 98304 B: 6 image rows x 64 w x 256B (128ch fp16)
#define ZSOFF XSSZ                    // 256 B zero block
#define BSOFF (XSSZ + 256)            // two B stages
#define DYNSM (BSOFF + 2 * BTILE)     // 135424 B

// ---------------- scratch (device globals; no allocs) ----------------
__device__ __align__(16) float  g_pooled[B_ * CIN];
__device__ __align__(16) float  g_alphas[B_ * KNUM];
__device__ __align__(16) float  g_aggb [B_ * COUT];
// agg weights laid out for the conv: [b][chunk(18)][o(128)][cidx(64)] fp16
__device__ __align__(16) __half g_aggw [(size_t)B_ * COUT * KTOT];
// x in NHWC fp16: [b][h][w][c]
__device__ __align__(16) __half g_x16  [(size_t)B_ * HWTOT * CIN];

__device__ __forceinline__ uint32_t smem_u32(const void* p) {
    return (uint32_t)__cvta_generic_to_shared(p);
}
__device__ __forceinline__ float warpsum(float v) {
#pragma unroll
    for (int o = 16; o; o >>= 1) v += __shfl_xor_sync(0xffffffffu, v, o);
    return v;
}

// ================= kernel 0: zero the pooled accumulator =================
__global__ void zero_pool_kernel() {
    int i = blockIdx.x * 256 + threadIdx.x;
    if (i < B_ * CIN) g_pooled[i] = 0.f;
}

// ================= kernel 1: NCHW fp32 -> NHWC fp16, fused avg-pool =================
__global__ void __launch_bounds__(256) convert_kernel(const float* __restrict__ x) {
    __shared__ char sm[128 * 256];
    const int t = threadIdx.x;
    const int pos0 = blockIdx.x * 128;
    const int b = blockIdx.y;
    const float* xb = x + ((size_t)b * CIN) * HWTOT;

#pragma unroll 4
    for (int i = 0; i < 64; ++i) {
        int e = i * 256 + t;
        int c = e >> 7;
        int p = e & 127;
        float v = xb[(size_t)c * HWTOT + pos0 + p];
        int boff = p * 256 + ((c * 2) ^ ((p & 15) << 4));
        *(__half*)(sm + boff) = __float2half_rn(v);
    }
    __syncthreads();
    if (t < 128) {
        int c = t;
        float s = 0.f;
#pragma unroll 8
        for (int p = 0; p < 128; ++p) {
            int boff = p * 256 + ((c * 2) ^ ((p & 15) << 4));
            s += __half2float(*(const __half*)(sm + boff));
        }
        atomicAdd(&g_pooled[b * CIN + c], s);
    }
    __syncthreads();
    __half* dstb = g_x16 + ((size_t)b * HWTOT + pos0) * CIN;
#pragma unroll
    for (int i = 0; i < 8; ++i) {
        int e = i * 256 + t;
        int p = e >> 4;
        int cc = e & 15;
        int boff = p * 256 + ((cc * 16) ^ ((p & 15) << 4));
        uint4 v = *(const uint4*)(sm + boff);
        ((uint4*)(dstb + (size_t)p * CIN))[cc] = v;
    }
}

// ================= kernel 2: MLP + scores + softmax + bias agg =================
__global__ void mlp_kernel(const float* __restrict__ prompt,
                           const float* __restrict__ w1, const float* __restrict__ b1,
                           const float* __restrict__ w2, const float* __restrict__ b2,
                           const float* __restrict__ kbias) {
    int b = blockIdx.x;
    int tid = threadIdx.x, wid = tid >> 5, lane = tid & 31;
    __shared__ float sp[CIN], sh[HIDD], ss[HIDD], ssc[KNUM], sal[KNUM];
    if (tid < CIN) sp[tid] = g_pooled[b * CIN + tid] * (1.f / (float)HWTOT);
    __syncthreads();
    for (int j = wid; j < HIDD; j += 16) {
        float p = 0.f;
        for (int c = lane; c < CIN; c += 32) p += sp[c] * w1[j * CIN + c];
        p = warpsum(p);
        if (lane == 0) sh[j] = fmaxf(p + b1[j], 0.f);
    }
    __syncthreads();
    for (int j = wid; j < HIDD; j += 16) {
        float p = 0.f;
        for (int c = lane; c < HIDD; c += 32) p += sh[c] * w2[j * HIDD + c];
        p = warpsum(p);
        if (lane == 0) ss[j] = p + b2[j];
    }
    __syncthreads();
    if (wid < KNUM) {
        float p = 0.f;
        for (int j = lane; j < HIDD; j += 32) p += ss[j] * prompt[wid * HIDD + j];
        p = warpsum(p);
        if (lane == 0) ssc[wid] = p;
    }
    __syncthreads();
    if (tid == 0) {
        float mx = -1e30f;
#pragma unroll
        for (int k = 0; k < KNUM; k++) mx = fmaxf(mx, ssc[k]);
        float den = 0.f, e[KNUM];
#pragma unroll
        for (int k = 0; k < KNUM; k++) { e[k] = expf(ssc[k] - mx); den += e[k]; }
#pragma unroll
        for (int k = 0; k < KNUM; k++) sal[k] = e[k] / den;
    }
    __syncthreads();
    if (tid < KNUM) g_alphas[b * KNUM + tid] = sal[tid];
    if (tid < COUT) {
        float a = 0.f;
#pragma unroll
        for (int k = 0; k < KNUM; k++) a += sal[k] * kbias[k * COUT + tid];
        g_aggb[b * COUT + tid] = a;
    }
}

// ================= kernel 3: weight aggregation v3 =================
// grid (128 o, 4 b-groups), 256 threads. Coalesced float4 reads, fp16 smem staging,
// coalesced uint4 writes in conv layout.
__global__ void __launch_bounds__(256) aggw_kernel(const float* __restrict__ kw) {
    __shared__ __half  kw_s[KNUM * KTOT];          // 18432 B
    __shared__ float   sal[8 * KNUM];              // this group's 8 samples
    __shared__ __align__(16) __half out_s[8 * KTOT]; // 18432 B
    const int t  = threadIdx.x;
    const int o  = blockIdx.x;
    const int b0 = blockIdx.y * 8;

    // stage kw[k][o][:] for all 8 k, float4-coalesced
#pragma unroll
    for (int i = 0; i < 9; ++i) {
        int idx4 = i * 256 + t;            // < 2304 float4
        int k = idx4 / 288;
        int r = idx4 - k * 288;
        float4 v = ((const float4*)kw)[((size_t)k * COUT + o) * 288 + r];
        __half2* d = (__half2*)(kw_s + k * KTOT + r * 4);
        d[0] = __floats2half2_rn(v.x, v.y);
        d[1] = __floats2half2_rn(v.z, v.w);
    }
    if (t < 64) sal[t] = g_alphas[b0 * KNUM + t];
    __syncthreads();

    // compute 8 b x 1152 j, write into out_s in conv k-order
#pragma unroll
    for (int bb = 0; bb < 8; ++bb) {
#pragma unroll
        for (int i = 0; i < 5; ++i) {
            int j = i * 256 + t;
            if (j < KTOT) {
                float a = 0.f;
#pragma unroll
                for (int k = 0; k < KNUM; ++k)
                    a += sal[bb * KNUM + k] * __half2float(kw_s[k * KTOT + j]);
                int ci = j / 9;
                int tap = j - ci * 9;
                int opos = (tap * 2 + (ci >> 6)) * 64 + (ci & 63);
                out_s[bb * KTOT + opos] = __float2half_rn(a);
            }
        }
    }
    __syncthreads();

    // write: 8 b x 18 segs x 8 uint4 = 1152 uint4
#pragma unroll
    for (int i = 0; i < 5; ++i) {
        int idx = i * 256 + t;
        if (idx < 1152) {
            int bb  = idx / 144;
            int r   = idx - bb * 144;
            int seg = r >> 3, part = r & 7;
            *(uint4*)(g_aggw + (size_t)(b0 + bb) * (COUT * KTOT) + seg * 8192 + o * 64 + part * 8)
                = *(const uint4*)(out_s + bb * KTOT + seg * 64 + part * 8);
        }
    }
}

// ================= kernel 4: conv — resident-x implicit GEMM (HMMA) =================
__device__ __forceinline__ void ldsm_x4(uint32_t& r0, uint32_t& r1, uint32_t& r2, uint32_t& r3,
                                        uint32_t addr) {
    asm volatile("ldmatrix.sync.aligned.m8n8.x4.shared.b16 {%0,%1,%2,%3}, [%4];"
                 : "=r"(r0), "=r"(r1), "=r"(r2), "=r"(r3) : "r"(addr));
}
__device__ __forceinline__ void mma16816(float* c, uint32_t a0, uint32_t a1, uint32_t a2,
                                         uint32_t a3, uint32_t b0, uint32_t b1) {
    asm volatile(
        "mma.sync.aligned.m16n8k16.row.col.f32.f16.f16.f32 "
        "{%0,%1,%2,%3}, {%4,%5,%6,%7}, {%8,%9}, {%0,%1,%2,%3};"
        : "+f"(c[0]), "+f"(c[1]), "+f"(c[2]), "+f"(c[3])
        : "r"(a0), "r"(a1), "r"(a2), "r"(a3), "r"(b0), "r"(b1));
}
__device__ __forceinline__ void cp16(uint32_t dst, const void* src, uint32_t srcsz) {
    asm volatile("cp.async.cg.shared.global [%0], [%1], 16, %2;"
                 :: "r"(dst), "l"(src), "r"(srcsz) : "memory");
}
__device__ __forceinline__ void cp_commit() {
    asm volatile("cp.async.commit_group;" ::: "memory");
}

extern __shared__ char conv_dyn[];

// CTA = (tile of 256 positions = 4 image rows, sample b). 512 threads, 16 warps.
__global__ void __launch_bounds__(512, 1) conv_kernel(float* __restrict__ out) {
    __shared__ float bias_s[COUT];
    const int t    = threadIdx.x;
    const int wid  = t >> 5;
    const int lane = t & 31;
    const int tile = blockIdx.x;     // 0..15
    const int b    = blockIdx.y;     // 0..31

    if (t < COUT) bias_s[t] = g_aggb[b * COUT + t];

    const uint32_t dynbase = smem_u32(conv_dyn);
    const uint32_t xsb = dynbase;
    const uint32_t zsb = dynbase + ZSOFF;
    const uint32_t bsb = dynbase + BSOFF;

    const __half* xb = g_x16 + (size_t)b * HWTOT * CIN;
    const uint4*  wb = (const uint4*)(g_aggw + (size_t)b * (COUT * KTOT));

    // zero the OOB block
    if (t < 16) *(uint4*)(conv_dyn + ZSOFF + t * 16) = make_uint4(0u, 0u, 0u, 0u);

    // ---- x tile: 6 image rows (tile*4-1 .. tile*4+4), 16B-block XOR swizzle ----
#pragma unroll
    for (int i = 0; i < 12; ++i) {
        int idx = i * 512 + t;               // < 6144 16B-blocks
        int smemrow = idx >> 4;              // 0..383 (lrow*64 + w)
        int blk = idx & 15;
        int lrow = smemrow >> 6;
        int w    = smemrow & 63;
        int srcrow = tile * 4 - 1 + lrow;
        bool v = (unsigned)srcrow < 64u;
        uint32_t dst = xsb + smemrow * 256 + ((blk ^ (smemrow & 15)) << 4);
        const __half* src = v ? (xb + ((size_t)(srcrow * 64 + w) * CIN) + blk * 8) : xb;
        cp16(dst, src, v ? 16u : 0u);
    }

    // ---- B chunk issue (1024 cp16 per chunk, 2 per thread) ----
    auto issueB = [&](int kcn) {
        const uint32_t stage = bsb + (uint32_t)(kcn & 1) * BTILE;
        const uint4* wsrc = wb + (size_t)kcn * 1024;
#pragma unroll
        for (int i = 0; i < 2; ++i) {
            int idx = i * 512 + t;
            int g = idx << 4;
            cp16(stage + (g >> 7) * ROWB + (g & 127), (const char*)(wsrc + idx), 16u);
        }
    };

    issueB(0);
    cp_commit();                              // group: x tile + B0

    // warp tiling: 8 (M) x 2 (N); warp tile = M32 x N64
    const int wm = wid >> 1;
    const int wn = wid & 1;
    const int m0 = wm * 32;
    const int n0 = wn * 64;

    float acc[2][8][4];
#pragma unroll
    for (int mt = 0; mt < 2; ++mt)
#pragma unroll
        for (int nt = 0; nt < 8; ++nt)
#pragma unroll
            for (int j = 0; j < 4; ++j) acc[mt][nt][j] = 0.f;

    // per-lane A row geometry (fixed): m = m0 + mt*16 + (lane&15)
    int mrowhi[2], mpw[2];
#pragma unroll
    for (int mt = 0; mt < 2; ++mt) {
        int m = m0 + mt * 16 + (lane & 15);
        mrowhi[mt] = m >> 6;                  // local image row 0..3
        mpw[mt]    = m & 63;
    }
    const int cq = lane >> 4;                 // A k-halves
    const int g  = lane >> 3;                 // B ldsm grouping
    const int rs = lane & 7;

    for (int kc = 0; kc < NCHUNK; ++kc) {
        if (kc < NCHUNK - 1) {
            issueB(kc + 1);
            cp_commit();
            asm volatile("cp.async.wait_group 1;" ::: "memory");
        } else {
            asm volatile("cp.async.wait_group 0;" ::: "memory");
        }
        __syncthreads();

        const int tap   = kc >> 1;
        const int chalf = kc & 1;
        const int rtap  = (tap * 11) >> 5;    // tap/3
        const int stap  = tap - rtap * 3;
        const uint32_t smB = bsb + (uint32_t)(kc & 1) * BTILE;

        // A lane row base per mt (shifted by tap, OOB -> zero block)
        uint32_t arow[2];
        int akey[2];
#pragma unroll
        for (int mt = 0; mt < 2; ++mt) {
            int lrow = mrowhi[mt] + rtap;     // 0..5 (OOB image rows are zero-filled)
            int iw   = mpw[mt] + stap - 1;
            bool v = (unsigned)iw < 64u;
            int smemrow = lrow * 64 + iw;
            arow[mt] = v ? (xsb + smemrow * 256) : zsb;
            akey[mt] = v ? (smemrow & 15) : 0;
        }

#pragma unroll
        for (int ks = 0; ks < 4; ++ks) {
            const int blk = chalf * 8 + ks * 2 + cq;
            uint32_t A0[4], A1[4];
            ldsm_x4(A0[0], A0[1], A0[2], A0[3], arow[0] + ((blk ^ akey[0]) << 4));
            ldsm_x4(A1[0], A1[1], A1[2], A1[3], arow[1] + ((blk ^ akey[1]) << 4));
#pragma unroll
            for (int bt = 0; bt < 4; ++bt) {
                uint32_t b0e, b1e, b0o, b1o;
                uint32_t baddr = smB + (n0 + bt * 16 + ((g >> 1) << 3) + rs) * ROWB
                               + (ks << 5) + ((g & 1) << 4);
                ldsm_x4(b0e, b1e, b0o, b1o, baddr);
                mma16816(acc[0][2 * bt],     A0[0], A0[1], A0[2], A0[3], b0e, b1e);
                mma16816(acc[0][2 * bt + 1], A0[0], A0[1], A0[2], A0[3], b0o, b1o);
                mma16816(acc[1][2 * bt],     A1[0], A1[1], A1[2], A1[3], b0e, b1e);
                mma16816(acc[1][2 * bt + 1], A1[0], A1[1], A1[2], A1[3], b0o, b1o);
            }
        }
        __syncthreads();
    }

    // ---- epilogue: 4 rounds (2 pos-halves x 2 o-halves) via smem transpose ----
    float* F = (float*)conv_dyn;              // 128 x 66 floats (reuses x region)
    float* outb = out + (size_t)b * COUT * HWTOT + tile * 256;
#pragma unroll
    for (int pr = 0; pr < 2; ++pr) {
#pragma unroll
        for (int orr = 0; orr < 2; ++orr) {
            if ((wm >> 2) == pr && wn == orr) {
#pragma unroll
                for (int mt = 0; mt < 2; ++mt)
#pragma unroll
                    for (int nt = 0; nt < 8; ++nt) {
                        int row = m0 - pr * 128 + mt * 16 + (lane >> 2);
                        int col = nt * 8 + 2 * (lane & 3);
                        *(float2*)&F[row * 66 + col]       = make_float2(acc[mt][nt][0], acc[mt][nt][1]);
                        *(float2*)&F[(row + 8) * 66 + col] = make_float2(acc[mt][nt][2], acc[mt][nt][3]);
                    }
            }
            __syncthreads();
#pragma unroll
            for (int i = 0; i < 4; ++i) {
                int e4 = i * 2048 + t * 4;     // 8192 floats, 4 per thread per iter
                int ol = e4 >> 7;
                int pp = e4 & 127;
                int oo = orr * 64 + ol;
                float4 v;
                v.x = F[(pp + 0) * 66 + ol] + bias_s[oo];
                v.y = F[(pp + 1) * 66 + ol] + bias_s[oo];
                v.z = F[(pp + 2) * 66 + ol] + bias_s[oo];
                v.w = F[(pp + 3) * 66 + ol] + bias_s[oo];
                *(float4*)(outb + (size_t)oo * HWTOT + pr * 128 + pp) = v;
            }
            __syncthreads();
        }
    }
}

// ================= launch =================
extern "C" void kernel_launch(void* const* d_in, const int* in_sizes, int n_in,
                              void* d_out, int out_size) {
    (void)out_size;
    const float* x = nullptr; const float* prompt = nullptr;
    const float* w1 = nullptr; const float* b1 = nullptr;
    const float* w2 = nullptr; const float* b2 = nullptr;
    const float* kw = nullptr; const float* kb = nullptr;
    for (int i = 0; i < n_in; ++i) {
        const float* ptr = (const float*)d_in[i];
        switch (in_sizes[i]) {
            case 16777216: x = ptr; break;
            case 4096:     prompt = ptr; break;
            case 65536:    w1 = ptr; break;
            case 262144:   w2 = ptr; break;
            case 1179648:  kw = ptr; break;
            case 1024:     kb = ptr; break;
            case 512:      if (!b1) b1 = ptr; else b2 = ptr; break;
            default: break;
        }
    }
    float* out = (float*)d_out;

    static bool attr_set = false;
    if (!attr_set) {
        cudaFuncSetAttribute(conv_kernel, cudaFuncAttributeMaxDynamicSharedMemorySize, DYNSM);
        attr_set = true;
    }

    zero_pool_kernel<<<(B_ * CIN + 255) / 256, 256>>>();
    convert_kernel<<<dim3(HWTOT / 128, B_), 256>>>(x);
    mlp_kernel<<<B_, 512>>>(prompt, w1, b1, w2, b2, kb);
    aggw_kernel<<<dim3(COUT, 4), 256>>>(kw);
    conv_kernel<<<dim3(HWTOT / 256, B_), 512, DYNSM>>>(out);
}